// round 1
// baseline (speedup 1.0000x reference)
#include <cuda_runtime.h>
#include <cuda_bf16.h>

// Problem constants
#define N_  128
#define D_  512
#define IC_ 32
#define OC_ 8
#define R_  4
// elements per (n,d) row of x / vars
#define ROW_ (IC_ * R_)            // 128 floats = 512 B
// elements per (n,d) of each output
#define OROW_ (OC_ * R_)           // 32 floats = 128 B
#define W_ELEMS_ (D_ * IC_ * OC_ * R_)   // 524288
#define OUT_HALF_ ((size_t)N_ * D_ * OC_ * R_)  // 2097152

// Block: 64 threads = one d, 64 consecutive n.  Grid = D_ * (N_/64) = 1024.
// Each thread owns one (n, d): 32 ic iterations, 64 accumulators.
__global__ __launch_bounds__(64, 8)
void logmix_kernel(const float4* __restrict__ x4,
                   const float4* __restrict__ v4,
                   const float*  __restrict__ w,
                   float* __restrict__ out)
{
    // smem: softmax(weights[d]) and its square, laid out [ic][oc] as float4 over r
    __shared__ float4 ws [IC_ * OC_];
    __shared__ float4 w2s[IC_ * OC_];

    const int d  = blockIdx.x >> 1;
    const int n  = ((blockIdx.x & 1) << 6) + threadIdx.x;

    // ---- Stage raw weights for this d into smem (coalesced), then softmax over ic ----
    float* wsf = reinterpret_cast<float*>(ws);
    float* w2f = reinterpret_cast<float*>(w2s);
    const float* wd = w + (size_t)d * (IC_ * OC_ * R_);
    #pragma unroll
    for (int i = 0; i < (IC_ * OC_ * R_) / 64; ++i)
        wsf[threadIdx.x + i * 64] = wd[threadIdx.x + i * 64];
    __syncthreads();

    if (threadIdx.x < OC_ * R_) {        // 32 threads, one per (oc, r) column
        const int j = threadIdx.x;       // column index; bank j -> conflict-free
        float s = 0.0f;
        #pragma unroll
        for (int ic = 0; ic < IC_; ++ic) {
            float e = __expf(wsf[ic * (OC_ * R_) + j]);
            wsf[ic * (OC_ * R_) + j] = e;
            s += e;
        }
        const float inv = 1.0f / s;
        #pragma unroll
        for (int ic = 0; ic < IC_; ++ic) {
            float wl = wsf[ic * (OC_ * R_) + j] * inv;
            wsf[ic * (OC_ * R_) + j] = wl;
            w2f[ic * (OC_ * R_) + j] = wl * wl;
        }
    }
    __syncthreads();

    // ---- Main loop: one (n,d) per thread ----
    const size_t row = ((size_t)n * D_ + d);
    const float4* xp = x4 + row * (ROW_ / 4);
    const float4* vp = v4 + row * (ROW_ / 4);

    float accP[OC_][R_];
    float accV[OC_][R_];
    #pragma unroll
    for (int oc = 0; oc < OC_; ++oc)
        #pragma unroll
        for (int r = 0; r < R_; ++r) { accP[oc][r] = 0.0f; accV[oc][r] = 0.0f; }

    #pragma unroll 4
    for (int ic = 0; ic < IC_; ++ic) {
        const float4 xv = __ldg(xp + ic);
        const float4 vv = __ldg(vp + ic);

        const float e0 = __expf(xv.x);
        const float e1 = __expf(xv.y);
        const float e2 = __expf(xv.z);
        const float e3 = __expf(xv.w);
        // t_r = exp(vars_r) + E_r^2   (left + right term fused: one accumulator, one log)
        const float t0 = fmaf(e0, e0, __expf(vv.x));
        const float t1 = fmaf(e1, e1, __expf(vv.y));
        const float t2 = fmaf(e2, e2, __expf(vv.z));
        const float t3 = fmaf(e3, e3, __expf(vv.w));

        #pragma unroll
        for (int oc = 0; oc < OC_; ++oc) {
            const float4 wl = ws [ic * OC_ + oc];   // broadcast LDS.128
            const float4 w2 = w2s[ic * OC_ + oc];
            accP[oc][0] = fmaf(wl.x, e0, accP[oc][0]);
            accP[oc][1] = fmaf(wl.y, e1, accP[oc][1]);
            accP[oc][2] = fmaf(wl.z, e2, accP[oc][2]);
            accP[oc][3] = fmaf(wl.w, e3, accP[oc][3]);
            accV[oc][0] = fmaf(w2.x, t0, accV[oc][0]);
            accV[oc][1] = fmaf(w2.y, t1, accV[oc][1]);
            accV[oc][2] = fmaf(w2.z, t2, accV[oc][2]);
            accV[oc][3] = fmaf(w2.w, t3, accV[oc][3]);
        }
    }

    // ---- Epilogue: logs + store (each thread writes two full 128B lines) ----
    float* outp = out + row * OROW_;
    float* outv = out + OUT_HALF_ + row * OROW_;
    #pragma unroll
    for (int oc = 0; oc < OC_; ++oc) {
        float4 p, q;
        p.x = __logf(accP[oc][0]); p.y = __logf(accP[oc][1]);
        p.z = __logf(accP[oc][2]); p.w = __logf(accP[oc][3]);
        q.x = __logf(accV[oc][0]); q.y = __logf(accV[oc][1]);
        q.z = __logf(accV[oc][2]); q.w = __logf(accV[oc][3]);
        reinterpret_cast<float4*>(outp)[oc] = p;
        reinterpret_cast<float4*>(outv)[oc] = q;
    }
}

extern "C" void kernel_launch(void* const* d_in, const int* in_sizes, int n_in,
                              void* d_out, int out_size)
{
    // Expected order: x, vars, weights. Be defensive: weights is the W_ELEMS_ one.
    const float* x = (const float*)d_in[0];
    const float* v = (const float*)d_in[1];
    const float* w = (const float*)d_in[2];
    if (n_in >= 3 && in_sizes[2] != W_ELEMS_) {
        // find weights by size, keep the other two in order
        int wi = -1;
        for (int i = 0; i < 3; ++i) if (in_sizes[i] == W_ELEMS_) { wi = i; break; }
        if (wi == 0)      { w = (const float*)d_in[0]; x = (const float*)d_in[1]; v = (const float*)d_in[2]; }
        else if (wi == 1) { x = (const float*)d_in[0]; w = (const float*)d_in[1]; v = (const float*)d_in[2]; }
    }

    dim3 grid(D_ * (N_ / 64));
    dim3 block(64);
    logmix_kernel<<<grid, block>>>((const float4*)x, (const float4*)v, w, (float*)d_out);
}

// round 2
// speedup vs baseline: 1.3089x; 1.3089x over previous
#include <cuda_runtime.h>
#include <cuda_bf16.h>

// Problem constants
#define N_  128
#define D_  512
#define IC_ 32
#define OC_ 8
#define R_  4
#define W_ELEMS_ (D_ * IC_ * OC_ * R_)          // 524288
#define OUT_HALF_ ((size_t)N_ * D_ * OC_ * R_)  // 2097152
#define SROW_ 36   // padded smem row stride in words (32 data + 4 pad)

// ---- packed fp32x2 helpers (Blackwell packed-FP32 pipe) ----
__device__ __forceinline__ unsigned long long pk2(float a, float b) {
    unsigned long long r;
    asm("mov.b64 %0, {%1, %2};" : "=l"(r) : "f"(a), "f"(b));
    return r;
}
__device__ __forceinline__ float2 upk2(unsigned long long a) {
    float lo, hi;
    asm("mov.b64 {%0, %1}, %2;" : "=f"(lo), "=f"(hi) : "l"(a));
    return make_float2(lo, hi);
}
__device__ __forceinline__ void fma2(unsigned long long& d,
                                     unsigned long long a, unsigned long long b) {
    asm("fma.rn.f32x2 %0, %1, %2, %0;" : "+l"(d) : "l"(a), "l"(b));
}

// Block: 128 threads = one d, all 128 n-rows. Grid = D_ = 512 -> single wave
// at 4 blocks/SM (128 regs, 44KB smem).
__global__ __launch_bounds__(128, 4)
void logmix_kernel(const float4* __restrict__ x4,
                   const float4* __restrict__ v4,
                   const float*  __restrict__ w,
                   float* __restrict__ out)
{
    __shared__ float xs[128 * SROW_];          // 18 KB, staged x chunk / P output
    __shared__ float vs[128 * SROW_];          // 18 KB, staged v chunk / V output
    __shared__ ulonglong2 wpk [IC_ * OC_];     // 4 KB  softmax(w) as f32x2 pairs
    __shared__ ulonglong2 w2pk[IC_ * OC_];     // 4 KB  softmax(w)^2

    const int t = threadIdx.x;
    const int d = blockIdx.x;

    // ---- Stage raw weights (coalesced), softmax over ic in smem ----
    float* wf  = reinterpret_cast<float*>(wpk);
    float* w2f = reinterpret_cast<float*>(w2pk);
    const float* wd = w + (size_t)d * (IC_ * OC_ * R_);
    #pragma unroll
    for (int i = 0; i < 8; ++i)
        wf[t + i * 128] = wd[t + i * 128];
    __syncthreads();

    if (t < 32) {                  // one thread per (oc,r) column; bank t -> conflict-free
        float s = 0.0f;
        #pragma unroll
        for (int ic = 0; ic < IC_; ++ic) {
            float e = __expf(wf[ic * 32 + t]);
            wf[ic * 32 + t] = e;
            s += e;
        }
        const float inv = 1.0f / s;
        #pragma unroll
        for (int ic = 0; ic < IC_; ++ic) {
            float wl = wf[ic * 32 + t] * inv;
            wf [ic * 32 + t] = wl;
            w2f[ic * 32 + t] = wl * wl;
        }
    }
    // (ordered before any wpk read by the stage-0 __syncthreads below)

    unsigned long long aP[OC_][2], aV[OC_][2];
    #pragma unroll
    for (int oc = 0; oc < OC_; ++oc) {
        aP[oc][0] = aP[oc][1] = 0ull;
        aV[oc][0] = aV[oc][1] = 0ull;
    }

    // loader role: thread t handles float4-slot fi of rows r0, r0+16, ..., r0+112
    const int fi = t & 7;
    const int r0 = t >> 3;
    const unsigned xs_base = (unsigned)__cvta_generic_to_shared(xs);
    const unsigned vs_base = (unsigned)__cvta_generic_to_shared(vs);

    #pragma unroll 1
    for (int s = 0; s < 4; ++s) {
        // ---- cooperative cp.async load of 8-ic chunk: 4 rows x 128B per warp instr ----
        #pragma unroll
        for (int j = 0; j < 8; ++j) {
            const int row = r0 + j * 16;
            const size_t g = ((size_t)row * D_ + d) * 32 + (size_t)(s * 8 + fi);
            const unsigned so = (unsigned)((row * SROW_ + fi * 4) * 4);
            asm volatile("cp.async.cg.shared.global [%0], [%1], 16;"
                         :: "r"(xs_base + so), "l"(x4 + g));
            asm volatile("cp.async.cg.shared.global [%0], [%1], 16;"
                         :: "r"(vs_base + so), "l"(v4 + g));
        }
        asm volatile("cp.async.commit_group;");
        asm volatile("cp.async.wait_group 0;" ::: "memory");
        __syncthreads();

        // ---- compute 8 ics for this thread's own row t ----
        const float4* xrow = reinterpret_cast<const float4*>(&xs[t * SROW_]);
        const float4* vrow = reinterpret_cast<const float4*>(&vs[t * SROW_]);
        #pragma unroll
        for (int ic = 0; ic < 8; ++ic) {
            const float4 xv = xrow[ic];
            const float4 vv = vrow[ic];
            const float e0 = __expf(xv.x), e1 = __expf(xv.y);
            const float e2 = __expf(xv.z), e3 = __expf(xv.w);
            // t_r = exp(vars_r) + E_r^2  (left+right logsumexp fused into one sum)
            const float t0 = fmaf(e0, e0, __expf(vv.x));
            const float t1 = fmaf(e1, e1, __expf(vv.y));
            const float t2 = fmaf(e2, e2, __expf(vv.z));
            const float t3 = fmaf(e3, e3, __expf(vv.w));
            const unsigned long long e01 = pk2(e0, e1), e23 = pk2(e2, e3);
            const unsigned long long t01 = pk2(t0, t1), t23 = pk2(t2, t3);
            const int icg = s * 8 + ic;
            #pragma unroll
            for (int oc = 0; oc < OC_; ++oc) {
                const ulonglong2 wu = wpk [icg * OC_ + oc];  // broadcast LDS.128
                const ulonglong2 qu = w2pk[icg * OC_ + oc];
                fma2(aP[oc][0], wu.x, e01);
                fma2(aP[oc][1], wu.y, e23);
                fma2(aV[oc][0], qu.x, t01);
                fma2(aV[oc][1], qu.y, t23);
            }
        }
        __syncthreads();   // before next stage overwrites xs/vs
    }

    // ---- Epilogue: logs into (reused) smem, own row only ----
    float4* prow = reinterpret_cast<float4*>(&xs[t * SROW_]);
    float4* qrow = reinterpret_cast<float4*>(&vs[t * SROW_]);
    #pragma unroll
    for (int oc = 0; oc < OC_; ++oc) {
        const float2 p0 = upk2(aP[oc][0]), p1 = upk2(aP[oc][1]);
        const float2 q0 = upk2(aV[oc][0]), q1 = upk2(aV[oc][1]);
        prow[oc] = make_float4(__logf(p0.x), __logf(p0.y), __logf(p1.x), __logf(p1.y));
        qrow[oc] = make_float4(__logf(q0.x), __logf(q0.y), __logf(q1.x), __logf(q1.y));
    }
    __syncthreads();

    // ---- Cooperative coalesced stores: 4 full 128B rows per warp instr ----
    float4* outP = reinterpret_cast<float4*>(out);
    float4* outV = reinterpret_cast<float4*>(out + OUT_HALF_);
    #pragma unroll
    for (int j = 0; j < 8; ++j) {
        const int row = r0 + j * 16;
        const size_t g = ((size_t)row * D_ + d) * 8 + fi;
        outP[g] = reinterpret_cast<const float4*>(&xs[row * SROW_])[fi];
        outV[g] = reinterpret_cast<const float4*>(&vs[row * SROW_])[fi];
    }
}

extern "C" void kernel_launch(void* const* d_in, const int* in_sizes, int n_in,
                              void* d_out, int out_size)
{
    // Expected order: x, vars, weights. Defensive: weights is the W_ELEMS_ one.
    const float* x = (const float*)d_in[0];
    const float* v = (const float*)d_in[1];
    const float* w = (const float*)d_in[2];
    if (n_in >= 3 && in_sizes[2] != W_ELEMS_) {
        int wi = -1;
        for (int i = 0; i < 3; ++i) if (in_sizes[i] == W_ELEMS_) { wi = i; break; }
        if (wi == 0)      { w = (const float*)d_in[0]; x = (const float*)d_in[1]; v = (const float*)d_in[2]; }
        else if (wi == 1) { x = (const float*)d_in[0]; w = (const float*)d_in[1]; v = (const float*)d_in[2]; }
    }

    logmix_kernel<<<D_, 128>>>((const float4*)x, (const float4*)v, w, (float*)d_out);
}